// round 2
// baseline (speedup 1.0000x reference)
#include <cuda_runtime.h>

// LieTransport: out[b,c,y,x,r] = bilinear_border_sample(h_prev[b,c,:,:,r], grid(b,y,x))
// grid = base_grid - flow*dt, align_corners=False, padding=border.
// Shapes: h_prev [4,16,128,128,64] f32, flow [4,2,128,128] f32, dt [4] f32.
// Memory-bound (~512 MB). Each thread handles 4 float4s (64 B of R) to amortize
// per-pixel coordinate math 4x and raise per-thread MLP to 16 loads.

#define B 4
#define C 16
#define H 128
#define W 128
#define R 64
#define R4 (R / 4)      // 16 float4 per pixel row
#define JPT 4           // float4s per thread

__global__ void __launch_bounds__(256)
lie_transport_kernel(const float4* __restrict__ h4,
                     const float* __restrict__ flow,
                     const float* __restrict__ dt,
                     float4* __restrict__ out4)
{
    // idx bits (fastest -> slowest): r4l (4), x (128), y (128), c (16), b (4)
    int idx = blockIdx.x * blockDim.x + threadIdx.x;   // 0 .. 2^22-1
    int r4l = idx & 3;                 // which of 4 base chunks; thread covers r4l + 4*j
    int x   = (idx >> 2) & (W - 1);
    int y   = (idx >> 9) & (H - 1);
    int c   = (idx >> 16) & (C - 1);
    int b   = idx >> 20;

    // ---- per-pixel sampling coordinates (computed once per 64 B of R) ----
    float d   = __ldg(&dt[b]);
    float fdx = __ldg(&flow[((b * 2 + 0) * H + y) * W + x]);
    float fdy = __ldg(&flow[((b * 2 + 1) * H + y) * W + x]);

    float gx = fmaf((float)x, 2.0f / (W - 1), -1.0f) - fdx * d;
    float gy = fmaf((float)y, 2.0f / (H - 1), -1.0f) - fdy * d;

    float xs = fminf(fmaxf(((gx + 1.0f) * (float)W - 1.0f) * 0.5f, 0.0f), (float)(W - 1));
    float ys = fminf(fmaxf(((gy + 1.0f) * (float)H - 1.0f) * 0.5f, 0.0f), (float)(H - 1));

    float x0f = floorf(xs);
    float y0f = floorf(ys);
    float wx = xs - x0f;
    float wy = ys - y0f;

    int x0 = (int)x0f;
    int y0 = (int)y0f;
    int x1 = min(x0 + 1, W - 1);
    int y1 = min(y0 + 1, H - 1);

    float w00 = (1.0f - wx) * (1.0f - wy);
    float w01 = wx * (1.0f - wy);
    float w10 = (1.0f - wx) * wy;
    float w11 = wx * wy;

    int bc = (b * C + c) * (H * W);
    const float4* p00 = h4 + (size_t)(bc + y0 * W + x0) * R4 + r4l;
    const float4* p01 = h4 + (size_t)(bc + y0 * W + x1) * R4 + r4l;
    const float4* p10 = h4 + (size_t)(bc + y1 * W + x0) * R4 + r4l;
    const float4* p11 = h4 + (size_t)(bc + y1 * W + x1) * R4 + r4l;

    float4* po = out4 + (size_t)(bc + y * W + x) * R4 + r4l;

    // ---- gather + blend 4 chunks; all 16 loads issued before first use ----
    float4 a00[JPT], a01[JPT], a10[JPT], a11[JPT];
#pragma unroll
    for (int j = 0; j < JPT; ++j) {
        a00[j] = __ldg(p00 + 4 * j);
        a01[j] = __ldg(p01 + 4 * j);
        a10[j] = __ldg(p10 + 4 * j);
        a11[j] = __ldg(p11 + 4 * j);
    }
#pragma unroll
    for (int j = 0; j < JPT; ++j) {
        float4 r;
        r.x = a00[j].x * w00; r.y = a00[j].y * w00; r.z = a00[j].z * w00; r.w = a00[j].w * w00;
        r.x = fmaf(a01[j].x, w01, r.x); r.y = fmaf(a01[j].y, w01, r.y);
        r.z = fmaf(a01[j].z, w01, r.z); r.w = fmaf(a01[j].w, w01, r.w);
        r.x = fmaf(a10[j].x, w10, r.x); r.y = fmaf(a10[j].y, w10, r.y);
        r.z = fmaf(a10[j].z, w10, r.z); r.w = fmaf(a10[j].w, w10, r.w);
        r.x = fmaf(a11[j].x, w11, r.x); r.y = fmaf(a11[j].y, w11, r.y);
        r.z = fmaf(a11[j].z, w11, r.z); r.w = fmaf(a11[j].w, w11, r.w);
        po[4 * j] = r;
    }
}

extern "C" void kernel_launch(void* const* d_in, const int* in_sizes, int n_in,
                              void* d_out, int out_size)
{
    const float* h_prev = nullptr;
    const float* flow   = nullptr;
    const float* dt     = nullptr;
    for (int i = 0; i < n_in; ++i) {
        if (in_sizes[i] == B * C * H * W * R)      h_prev = (const float*)d_in[i];
        else if (in_sizes[i] == B * 2 * H * W)     flow   = (const float*)d_in[i];
        else if (in_sizes[i] == B)                 dt     = (const float*)d_in[i];
    }

    int total = B * C * H * W * (R4 / JPT);        // 4,194,304 threads
    int threads = 256;
    int blocks = total / threads;                  // 16,384

    lie_transport_kernel<<<blocks, threads>>>(
        (const float4*)h_prev, flow, dt, (float4*)d_out);
}

// round 3
// speedup vs baseline: 1.0138x; 1.0138x over previous
#include <cuda_runtime.h>

// LieTransport: out[b,c,y,x,r] = bilinear_border_sample(h_prev[b,c,:,:,r], grid(b,y,x))
// Shapes: h_prev [4,16,128,128,64] f32, flow [4,2,128,128] f32, dt [4] f32.
// Memory-bound (~493 MB DRAM floor). Layout: 8 lanes per pixel, each thread does
// 2 float4s at r4l and r4l+8 -> every warp load instruction covers full 128B lines
// (4 lines/warp/load), coordinate math amortized 2x vs one-chunk-per-thread.

#define B 4
#define C 16
#define H 128
#define W 128
#define R 64
#define R4 (R / 4)      // 16 float4 per pixel row

__global__ void __launch_bounds__(256)
lie_transport_kernel(const float4* __restrict__ h4,
                     const float* __restrict__ flow,
                     const float* __restrict__ dt,
                     float4* __restrict__ out4)
{
    // idx bits (fastest -> slowest): r4l (8), x (128), y (128), c (16), b (4)
    int idx = blockIdx.x * blockDim.x + threadIdx.x;   // 0 .. 2^23-1
    int r4l = idx & 7;                  // thread covers r4l and r4l + 8
    int x   = (idx >> 3) & (W - 1);
    int y   = (idx >> 10) & (H - 1);
    int c   = (idx >> 17) & (C - 1);
    int b   = idx >> 21;

    // ---- per-pixel sampling coordinates ----
    float d   = __ldg(&dt[b]);
    float fdx = __ldg(&flow[((b * 2 + 0) * H + y) * W + x]);
    float fdy = __ldg(&flow[((b * 2 + 1) * H + y) * W + x]);

    float gx = fmaf((float)x, 2.0f / (W - 1), -1.0f) - fdx * d;
    float gy = fmaf((float)y, 2.0f / (H - 1), -1.0f) - fdy * d;

    float xs = fminf(fmaxf(((gx + 1.0f) * (float)W - 1.0f) * 0.5f, 0.0f), (float)(W - 1));
    float ys = fminf(fmaxf(((gy + 1.0f) * (float)H - 1.0f) * 0.5f, 0.0f), (float)(H - 1));

    float x0f = floorf(xs);
    float y0f = floorf(ys);
    float wx = xs - x0f;
    float wy = ys - y0f;

    int x0 = (int)x0f;
    int y0 = (int)y0f;
    int x1 = min(x0 + 1, W - 1);
    int y1 = min(y0 + 1, H - 1);

    float w00 = (1.0f - wx) * (1.0f - wy);
    float w01 = wx * (1.0f - wy);
    float w10 = (1.0f - wx) * wy;
    float w11 = wx * wy;

    int bc = (b * C + c) * (H * W);
    const float4* p00 = h4 + (size_t)(bc + y0 * W + x0) * R4 + r4l;
    const float4* p01 = h4 + (size_t)(bc + y0 * W + x1) * R4 + r4l;
    const float4* p10 = h4 + (size_t)(bc + y1 * W + x0) * R4 + r4l;
    const float4* p11 = h4 + (size_t)(bc + y1 * W + x1) * R4 + r4l;

    float4* po = out4 + (size_t)(bc + y * W + x) * R4 + r4l;

    // ---- issue all 8 gathers, then blend ----
    float4 a00 = __ldg(p00);
    float4 a01 = __ldg(p01);
    float4 a10 = __ldg(p10);
    float4 a11 = __ldg(p11);
    float4 b00 = __ldg(p00 + 8);
    float4 b01 = __ldg(p01 + 8);
    float4 b10 = __ldg(p10 + 8);
    float4 b11 = __ldg(p11 + 8);

    float4 r0;
    r0.x = a00.x * w00; r0.y = a00.y * w00; r0.z = a00.z * w00; r0.w = a00.w * w00;
    r0.x = fmaf(a01.x, w01, r0.x); r0.y = fmaf(a01.y, w01, r0.y);
    r0.z = fmaf(a01.z, w01, r0.z); r0.w = fmaf(a01.w, w01, r0.w);
    r0.x = fmaf(a10.x, w10, r0.x); r0.y = fmaf(a10.y, w10, r0.y);
    r0.z = fmaf(a10.z, w10, r0.z); r0.w = fmaf(a10.w, w10, r0.w);
    r0.x = fmaf(a11.x, w11, r0.x); r0.y = fmaf(a11.y, w11, r0.y);
    r0.z = fmaf(a11.z, w11, r0.z); r0.w = fmaf(a11.w, w11, r0.w);
    __stcs(po, r0);

    float4 r1;
    r1.x = b00.x * w00; r1.y = b00.y * w00; r1.z = b00.z * w00; r1.w = b00.w * w00;
    r1.x = fmaf(b01.x, w01, r1.x); r1.y = fmaf(b01.y, w01, r1.y);
    r1.z = fmaf(b01.z, w01, r1.z); r1.w = fmaf(b01.w, w01, r1.w);
    r1.x = fmaf(b10.x, w10, r1.x); r1.y = fmaf(b10.y, w10, r1.y);
    r1.z = fmaf(b10.z, w10, r1.z); r1.w = fmaf(b10.w, w10, r1.w);
    r1.x = fmaf(b11.x, w11, r1.x); r1.y = fmaf(b11.y, w11, r1.y);
    r1.z = fmaf(b11.z, w11, r1.z); r1.w = fmaf(b11.w, w11, r1.w);
    __stcs(po + 8, r1);
}

extern "C" void kernel_launch(void* const* d_in, const int* in_sizes, int n_in,
                              void* d_out, int out_size)
{
    const float* h_prev = nullptr;
    const float* flow   = nullptr;
    const float* dt     = nullptr;
    for (int i = 0; i < n_in; ++i) {
        if (in_sizes[i] == B * C * H * W * R)      h_prev = (const float*)d_in[i];
        else if (in_sizes[i] == B * 2 * H * W)     flow   = (const float*)d_in[i];
        else if (in_sizes[i] == B)                 dt     = (const float*)d_in[i];
    }

    int total = B * C * H * W * (R4 / 2);          // 8,388,608 threads
    int threads = 256;
    int blocks = total / threads;                  // 32,768

    lie_transport_kernel<<<blocks, threads>>>(
        (const float4*)h_prev, flow, dt, (float4*)d_out);
}

// round 4
// speedup vs baseline: 1.0721x; 1.0576x over previous
#include <cuda_runtime.h>

// LieTransport: out[b,c,y,x,r] = bilinear_border_sample(h_prev[b,c,:,:,r], grid(b,y,x))
// Shapes: h_prev [4,16,128,128,64] f32, flow [4,2,128,128] f32, dt [4] f32.
// Latency-limited gather (~493 MB DRAM floor). Winning config: one float4 per
// thread, 16 lanes per pixel (full 128B-line coalescing). This round: factored
// lerp (12 FMA, no corner-weight regs) + pure int32 indexing to cut registers
// and issue pressure, raising occupancy / outstanding loads.

#define B 4
#define C 16
#define H 128
#define W 128
#define R 64
#define R4 (R / 4)  // 16 float4 per pixel

__device__ __forceinline__ float4 f4_lerp(float4 a, float4 b, float t) {
    // a + t*(b-a)
    float4 r;
    r.x = fmaf(t, b.x - a.x, a.x);
    r.y = fmaf(t, b.y - a.y, a.y);
    r.z = fmaf(t, b.z - a.z, a.z);
    r.w = fmaf(t, b.w - a.w, a.w);
    return r;
}

__global__ void __launch_bounds__(256)
lie_transport_kernel(const float4* __restrict__ h4,
                     const float* __restrict__ flow,
                     const float* __restrict__ dt,
                     float4* __restrict__ out4)
{
    // idx bits (fastest -> slowest): r4 (16), x (128), y (128), c (16), b (4)
    int idx = blockIdx.x * blockDim.x + threadIdx.x;   // 0 .. 2^24-1
    int r4 = idx & (R4 - 1);
    int x  = (idx >> 4) & (W - 1);
    int y  = (idx >> 11) & (H - 1);
    int c  = (idx >> 18) & (C - 1);
    int b  = idx >> 22;

    // ---- per-pixel sampling coordinates ----
    float d   = __ldg(&dt[b]);
    float fdx = __ldg(&flow[((b * 2 + 0) * H + y) * W + x]);
    float fdy = __ldg(&flow[((b * 2 + 1) * H + y) * W + x]);

    float gx = fmaf((float)x, 2.0f / (W - 1), -1.0f) - fdx * d;
    float gy = fmaf((float)y, 2.0f / (H - 1), -1.0f) - fdy * d;

    float xs = fminf(fmaxf(((gx + 1.0f) * (float)W - 1.0f) * 0.5f, 0.0f), (float)(W - 1));
    float ys = fminf(fmaxf(((gy + 1.0f) * (float)H - 1.0f) * 0.5f, 0.0f), (float)(H - 1));

    float x0f = floorf(xs);
    float y0f = floorf(ys);
    float wx = xs - x0f;
    float wy = ys - y0f;

    int x0 = (int)x0f;
    int y0 = (int)y0f;
    int x1 = min(x0 + 1, W - 1);
    int y1 = min(y0 + 1, H - 1);

    // int32 float4-indices (max 2^26, byte offsets 2^30: fits)
    int bc  = (b * C + c) * (H * W);
    int i00 = (bc + y0 * W + x0) * R4 + r4;
    int i01 = (bc + y0 * W + x1) * R4 + r4;
    int i10 = (bc + y1 * W + x0) * R4 + r4;
    int i11 = (bc + y1 * W + x1) * R4 + r4;

    float4 v00 = __ldg(h4 + i00);
    float4 v01 = __ldg(h4 + i01);
    float4 v10 = __ldg(h4 + i10);
    float4 v11 = __ldg(h4 + i11);

    float4 top = f4_lerp(v00, v01, wx);
    float4 bot = f4_lerp(v10, v11, wx);
    out4[idx]  = f4_lerp(top, bot, wy);
}

extern "C" void kernel_launch(void* const* d_in, const int* in_sizes, int n_in,
                              void* d_out, int out_size)
{
    const float* h_prev = nullptr;
    const float* flow   = nullptr;
    const float* dt     = nullptr;
    for (int i = 0; i < n_in; ++i) {
        if (in_sizes[i] == B * C * H * W * R)      h_prev = (const float*)d_in[i];
        else if (in_sizes[i] == B * 2 * H * W)     flow   = (const float*)d_in[i];
        else if (in_sizes[i] == B)                 dt     = (const float*)d_in[i];
    }

    int total = B * C * H * W * R4;                // 16,777,216 threads
    int threads = 256;
    int blocks = total / threads;                  // 65,536

    lie_transport_kernel<<<blocks, threads>>>(
        (const float4*)h_prev, flow, dt, (float4*)d_out);
}